// round 8
// baseline (speedup 1.0000x reference)
#include <cuda_runtime.h>
#include <math_constants.h>

#define Dk 2048
#define Bk 32
#define LOG2E 1.4426950408889634f
#define KSPLIT 8
#define KCHUNK (Dk / KSPLIT)        // 256
#define NCOLS  64
#define XPAD   68                   // 272B rows: 16B-aligned, conflict-free

typedef unsigned long long u64;
typedef unsigned int u32;

// Scratch ---------------------------------------------------------------------
__device__ float  g_part[3 * KSPLIT * Dk * Bk];  // [mat][ks][col][b]
__device__ float  g_q2[Bk * Dk];                 // (x@WqT + bq) * log2e
__device__ float  g_k [Bk * Dk];
__device__ float  g_v [Bk * Dk];
__device__ float4 g_kmp4[Bk * Dk / 2];           // pairs {k0,k1,m0,m1}
__device__ float4 g_c4 [Bk * Dk / 4];            // c packed 4-wide

__device__ __forceinline__ float ex2f(float x) {
    float r; asm("ex2.approx.f32 %0, %1;" : "=f"(r) : "f"(x)); return r;
}
__device__ __forceinline__ u64 pk2(float a, float b) {
    u64 r;
    asm("mov.b64 %0, {%1,%2};" : "=l"(r)
        : "r"(__float_as_uint(a)), "r"(__float_as_uint(b)));
    return r;
}
__device__ __forceinline__ void upk2(u64 v, u32 &a, u32 &b) {
    asm("mov.b64 {%0,%1}, %2;" : "=r"(a), "=r"(b) : "l"(v));
}
#define FMAX2(d,a,b,c) asm("fma.rn.f32x2 %0, %1, %2, %3;" : "=l"(d) : "l"(a), "l"(b), "l"(c))
#define ADDX2(d,a,b)   asm("add.rn.f32x2 %0, %1, %2;"     : "=l"(d) : "l"(a), "l"(b))

// Packed-poly exp2 for a pair of non-positive exponents. deg-4, rel err ~4e-5.
struct ExpC { u64 BIG2, NBIG2, NEG12, C4, C3, C2, C1, C0; };
__device__ __forceinline__ ExpC make_expc() {
    ExpC c;
    c.BIG2  = pk2( 12582912.0f,  12582912.0f);
    c.NBIG2 = pk2(-12582912.0f, -12582912.0f);
    c.NEG12 = pk2(-1.0f, -1.0f);
    c.C4 = pk2(0.0096181291f, 0.0096181291f);
    c.C3 = pk2(0.0555041087f, 0.0555041087f);
    c.C2 = pk2(0.2402265070f, 0.2402265070f);
    c.C1 = pk2(0.6931471806f, 0.6931471806f);
    c.C0 = pk2(1.0f, 1.0f);
    return c;
}
__device__ __forceinline__ void exp2pair(float e0, float e1, const ExpC &K,
                                         float &r0, float &r1) {
    e0 = fmaxf(e0, -125.0f); e1 = fmaxf(e1, -125.0f);
    u64 E = pk2(e0, e1);
    u64 T; ADDX2(T, E, K.BIG2);       // t = e + 1.5*2^23  (n = round(e) in mantissa)
    u64 N; ADDX2(N, T, K.NBIG2);      // n
    u64 F; FMAX2(F, N, K.NEG12, E);   // f = e - n in [-0.5, 0.5]
    u64 P; FMAX2(P, F, K.C4, K.C3);   // Horner deg-4 for 2^f
    FMAX2(P, P, F, K.C2);
    FMAX2(P, P, F, K.C1);
    FMAX2(P, P, F, K.C0);
    u32 t0, t1, p0, p1;
    upk2(T, t0, t1); upk2(P, p0, p1);
    r0 = __uint_as_float(p0 + (t0 << 23));   // splice 2^n into exponent
    r1 = __uint_as_float(p1 + (t1 << 23));
}

// ---------------------------------------------------------------------------
// K1: split-K projection GEMM partials, packed f32x2 FFMA (k-paired lanes).
// ---------------------------------------------------------------------------
__global__ __launch_bounds__(256, 1) void proj_kernel(
    const float* __restrict__ x,
    const float* __restrict__ Wq,
    const float* __restrict__ Wk,
    const float* __restrict__ Wv)
{
    __shared__ float xs[32 * XPAD];
    __shared__ float ws[NCOLS * XPAD];

    const int bx = blockIdx.x;
    const int mat = bx / (32 * KSPLIT);
    const int rem = bx % (32 * KSPLIT);
    const int colbase = (rem / KSPLIT) * NCOLS;
    const int ks  = rem % KSPLIT;
    const int k0base = ks * KCHUNK;

    const float* W = (mat == 0) ? Wq : (mat == 1) ? Wk : Wv;

    const int tid  = threadIdx.x;
    const int lane = tid & 31;           // batch
    const int wid  = tid >> 5;           // warp -> 8 cols

    u64 acc2[8];
    #pragma unroll
    for (int c = 0; c < 8; c++) acc2[c] = 0ull;

    for (int s = 0; s < KCHUNK / 64; s++) {
        const int k0 = k0base + s * 64;
        #pragma unroll
        for (int r = 0; r < 2; r++) {
            int idx = r * 256 + tid;
            int b = idx >> 4, kv = idx & 15;
            float4 t = *(const float4*)(x + b * Dk + k0 + kv * 4);
            *(float4*)(xs + b * XPAD + kv * 4) = t;
        }
        #pragma unroll
        for (int r = 0; r < 4; r++) {
            int idx = r * 256 + tid;
            int c = idx >> 4, kv = idx & 15;
            float4 t = *(const float4*)(W + (colbase + c) * Dk + k0 + kv * 4);
            *(float4*)(ws + c * XPAD + kv * 4) = t;
        }
        __syncthreads();

        const float* xrow  = xs + lane * XPAD;
        const float* wbase = ws + (wid * 8) * XPAD;

        #pragma unroll 4
        for (int k = 0; k < 64; k += 4) {
            double2 xv = *(const double2*)(xrow + k);        // (x_k,x_k+1),(x_k+2,x_k+3)
            u64 x01 = __double_as_longlong(xv.x);
            u64 x23 = __double_as_longlong(xv.y);
            #pragma unroll
            for (int c = 0; c < 8; c++) {
                double2 wv = *(const double2*)(wbase + c * XPAD + k);  // broadcast
                u64 w01 = __double_as_longlong(wv.x);
                u64 w23 = __double_as_longlong(wv.y);
                FMAX2(acc2[c], x01, w01, acc2[c]);
                FMAX2(acc2[c], x23, w23, acc2[c]);
            }
        }
        __syncthreads();
    }

    float* dst = g_part + (((mat * KSPLIT + ks) * Dk) + colbase + wid * 8) * Bk + lane;
    #pragma unroll
    for (int c = 0; c < 8; c++) {
        u32 lo, hi; upk2(acc2[c], lo, hi);
        dst[c * Bk] = __uint_as_float(lo) + __uint_as_float(hi);
    }
}

// ---------------------------------------------------------------------------
// K1b: reduce KSPLIT partials + bias + scale + transpose.
// ---------------------------------------------------------------------------
__global__ __launch_bounds__(256, 1) void reduce_kernel(
    const float* __restrict__ bq,
    const float* __restrict__ bk,
    const float* __restrict__ bv)
{
    __shared__ float s[NCOLS][33];

    const int mat = blockIdx.x / 32;
    const int colbase = (blockIdx.x % 32) * NCOLS;
    const int tid = threadIdx.x;

    const float* bias; float* out; float scale;
    if (mat == 0)      { bias = bq; out = g_q2; scale = LOG2E; }
    else if (mat == 1) { bias = bk; out = g_k;  scale = 1.0f; }
    else               { bias = bv; out = g_v;  scale = 1.0f; }

    const float* src = g_part + (mat * KSPLIT * Dk + colbase) * Bk;

    #pragma unroll
    for (int it = 0; it < 8; it++) {
        int e = it * 256 + tid;
        int c = e >> 5, b = e & 31;
        float sum = 0.f;
        #pragma unroll
        for (int p = 0; p < KSPLIT; p++)
            sum += src[p * Dk * Bk + c * Bk + b];
        s[c][b] = sum;
    }
    __syncthreads();

    #pragma unroll
    for (int it = 0; it < 8; it++) {
        int e = it * 256 + tid;
        int b = e >> 6, c = e & 63;
        out[b * Dk + colbase + c] = (s[c][b] + bias[colbase + c]) * scale;
    }
}

// ---------------------------------------------------------------------------
// K2 (pass1): S_j, then write pair-packed {k,negm2} and c=v/S.
// Hybrid exp: 12/16 via MUFU ex2, 4/16 via packed poly.
// ---------------------------------------------------------------------------
__global__ __launch_bounds__(128, 1) void pass1_kernel()
{
    __shared__ float4 q2s4[Dk / 4];          // 8 KB
    __shared__ float wmx[4], wmn[4];

    const int b   = blockIdx.y;
    const int tid = threadIdx.x;
    const int j   = blockIdx.x * 128 + tid;
    const float4* q2 = (const float4*)(g_q2 + b * Dk);

    float mx = -CUDART_INF_F, mn = CUDART_INF_F;
    for (int i = tid; i < Dk / 4; i += 128) {
        float4 v = q2[i];
        q2s4[i] = v;
        mx = fmaxf(mx, fmaxf(fmaxf(v.x, v.y), fmaxf(v.z, v.w)));
        mn = fminf(mn, fminf(fminf(v.x, v.y), fminf(v.z, v.w)));
    }
    #pragma unroll
    for (int o = 16; o; o >>= 1) {
        mx = fmaxf(mx, __shfl_xor_sync(0xffffffffu, mx, o));
        mn = fminf(mn, __shfl_xor_sync(0xffffffffu, mn, o));
    }
    if ((tid & 31) == 0) { wmx[tid >> 5] = mx; wmn[tid >> 5] = mn; }
    __syncthreads();
    mx = fmaxf(fmaxf(wmx[0], wmx[1]), fmaxf(wmx[2], wmx[3]));
    mn = fminf(fminf(wmn[0], wmn[1]), fminf(wmn[2], wmn[3]));

    const float kj    = g_k[b * Dk + j];
    const float negm2 = -((kj > 0.0f) ? mx : mn) * kj;   // exponent <= 0
    const ExpC K = make_expc();

    float a0=0.f,a1=0.f,a2=0.f,a3=0.f,a4=0.f,a5=0.f,a6=0.f,a7=0.f;
    #pragma unroll 1
    for (int i0 = 0; i0 < Dk / 4; i0 += 4) {
        float4 q0 = q2s4[i0 + 0];
        float4 q1 = q2s4[i0 + 1];
        float4 q2v = q2s4[i0 + 2];
        float4 q3 = q2s4[i0 + 3];
        // 12 MUFU exps
        a0 += ex2f(fmaf(q0.x, kj, negm2));
        a1 += ex2f(fmaf(q0.y, kj, negm2));
        a2 += ex2f(fmaf(q0.z, kj, negm2));
        a3 += ex2f(fmaf(q0.w, kj, negm2));
        a4 += ex2f(fmaf(q1.x, kj, negm2));
        a5 += ex2f(fmaf(q1.y, kj, negm2));
        a0 += ex2f(fmaf(q1.z, kj, negm2));
        a1 += ex2f(fmaf(q1.w, kj, negm2));
        a2 += ex2f(fmaf(q2v.x, kj, negm2));
        a3 += ex2f(fmaf(q2v.y, kj, negm2));
        a4 += ex2f(fmaf(q2v.z, kj, negm2));
        a5 += ex2f(fmaf(q2v.w, kj, negm2));
        // 4 poly exps
        float r0, r1;
        exp2pair(fmaf(q3.x, kj, negm2), fmaf(q3.y, kj, negm2), K, r0, r1);
        a6 += r0; a7 += r1;
        exp2pair(fmaf(q3.z, kj, negm2), fmaf(q3.w, kj, negm2), K, r0, r1);
        a6 += r0; a7 += r1;
    }
    const float S = ((a0 + a1) + (a2 + a3)) + ((a4 + a5) + (a6 + a7));  // >= 1
    const float c = __fdividef(g_v[b * Dk + j], S);

    // scatter packed outputs
    float* kmpf = (float*)g_kmp4;
    int base = (b * (Dk >> 1) + (j >> 1)) * 4 + (j & 1);
    kmpf[base]     = kj;
    kmpf[base + 2] = negm2;
    ((float*)g_c4)[b * Dk + j] = c;
}

// ---------------------------------------------------------------------------
// K3 (pass2): out[b][i] = sum_j c_j * exp2(q2_i*k_j - m2_j).  Hybrid 12/4.
// ---------------------------------------------------------------------------
__global__ __launch_bounds__(128, 1) void pass2_kernel(float* __restrict__ out)
{
    __shared__ float4 kmps[Dk / 2];          // 16 KB
    __shared__ float4 cs[Dk / 4];            // 8 KB

    const int b   = blockIdx.y;
    const int tid = threadIdx.x;
    const int i   = blockIdx.x * 128 + tid;

    const float4* kmsrc = g_kmp4 + b * (Dk / 2);
    const float4* csrc  = g_c4  + b * (Dk / 4);
    for (int idx = tid; idx < Dk / 2; idx += 128) kmps[idx] = kmsrc[idx];
    for (int idx = tid; idx < Dk / 4; idx += 128) cs[idx]   = csrc[idx];
    __syncthreads();

    const float qi = g_q2[b * Dk + i];
    const ExpC K = make_expc();

    float a0=0.f,a1=0.f,a2=0.f,a3=0.f,a4=0.f,a5=0.f,a6=0.f,a7=0.f;
    #pragma unroll 1
    for (int j0 = 0; j0 < Dk; j0 += 16) {
        const int pr = j0 >> 1;
        float4 km0 = kmps[pr + 0];
        float4 km1 = kmps[pr + 1];
        float4 km2 = kmps[pr + 2];
        float4 km3 = kmps[pr + 3];
        float4 km4 = kmps[pr + 4];
        float4 km5 = kmps[pr + 5];
        float4 km6 = kmps[pr + 6];
        float4 km7 = kmps[pr + 7];
        float4 c0 = cs[(j0 >> 2) + 0];
        float4 c1 = cs[(j0 >> 2) + 1];
        float4 c2 = cs[(j0 >> 2) + 2];
        float4 c3 = cs[(j0 >> 2) + 3];
        // 12 MUFU exps (pairs 0..5)
        a0 = fmaf(ex2f(fmaf(qi, km0.x, km0.z)), c0.x, a0);
        a1 = fmaf(ex2f(fmaf(qi, km0.y, km0.w)), c0.y, a1);
        a2 = fmaf(ex2f(fmaf(qi, km1.x, km1.z)), c0.z, a2);
        a3 = fmaf(ex2f(fmaf(qi, km1.y, km1.w)), c0.w, a3);
        a4 = fmaf(ex2f(fmaf(qi, km2.x, km2.z)), c1.x, a4);
        a5 = fmaf(ex2f(fmaf(qi, km2.y, km2.w)), c1.y, a5);
        a0 = fmaf(ex2f(fmaf(qi, km3.x, km3.z)), c1.z, a0);
        a1 = fmaf(ex2f(fmaf(qi, km3.y, km3.w)), c1.w, a1);
        a2 = fmaf(ex2f(fmaf(qi, km4.x, km4.z)), c2.x, a2);
        a3 = fmaf(ex2f(fmaf(qi, km4.y, km4.w)), c2.y, a3);
        a4 = fmaf(ex2f(fmaf(qi, km5.x, km5.z)), c2.z, a4);
        a5 = fmaf(ex2f(fmaf(qi, km5.y, km5.w)), c2.w, a5);
        // 4 poly exps (pairs 6,7)
        float r0, r1;
        exp2pair(fmaf(qi, km6.x, km6.z), fmaf(qi, km6.y, km6.w), K, r0, r1);
        a6 = fmaf(r0, c3.x, a6);
        a7 = fmaf(r1, c3.y, a7);
        exp2pair(fmaf(qi, km7.x, km7.z), fmaf(qi, km7.y, km7.w), K, r0, r1);
        a6 = fmaf(r0, c3.z, a6);
        a7 = fmaf(r1, c3.w, a7);
    }
    out[b * Dk + i] = ((a0 + a1) + (a2 + a3)) + ((a4 + a5) + (a6 + a7));
}

// ---------------------------------------------------------------------------
extern "C" void kernel_launch(void* const* d_in, const int* in_sizes, int n_in,
                              void* d_out, int out_size)
{
    (void)in_sizes; (void)n_in; (void)out_size;
    const float* x  = (const float*)d_in[0];
    const float* Wq = (const float*)d_in[1];
    const float* bq = (const float*)d_in[2];
    const float* Wk = (const float*)d_in[3];
    const float* bk = (const float*)d_in[4];
    const float* Wv = (const float*)d_in[5];
    const float* bv = (const float*)d_in[6];
    float* out = (float*)d_out;

    proj_kernel<<<3 * 32 * KSPLIT, 256>>>(x, Wq, Wk, Wv);
    reduce_kernel<<<3 * 32, 256>>>(bq, bk, bv);

    dim3 grid_s(Dk / 128, Bk);   // (16, 32)
    pass1_kernel<<<grid_s, 128>>>();
    pass2_kernel<<<grid_s, 128>>>(out);
}

// round 9
// speedup vs baseline: 1.6815x; 1.6815x over previous
#include <cuda_runtime.h>
#include <math_constants.h>

#define Dk 2048
#define Bk 32
#define LOG2E 1.4426950408889634f
#define KSPLIT 8
#define KCHUNK (Dk / KSPLIT)        // 256
#define NCOLS  64
#define XPAD   68                   // 272B rows: 16B-aligned, conflict-free

// Scratch (no allocations allowed) -------------------------------------------
__device__ float  g_part[3 * KSPLIT * Dk * Bk];  // [mat][ks][col][b]
__device__ float  g_q2[Bk * Dk];   // (x@WqT + bq) * log2e
__device__ float  g_k [Bk * Dk];
__device__ float  g_v [Bk * Dk];
__device__ float4 g_kmc[Bk * Dk];  // {k_j, -m2_j, v_j/S_j, 0}

__device__ __forceinline__ float ex2f(float x) {
    float r; asm("ex2.approx.f32 %0, %1;" : "=f"(r) : "f"(x)); return r;
}

// ---------------------------------------------------------------------------
// K1: split-K projection GEMM partials (R3 version, scalar FMA).
// grid.x = 3 * 32 * KSPLIT, block 256 = 8 warps; warp -> 8 cols, lane -> batch.
// ---------------------------------------------------------------------------
__global__ __launch_bounds__(256, 1) void proj_kernel(
    const float* __restrict__ x,
    const float* __restrict__ Wq,
    const float* __restrict__ Wk,
    const float* __restrict__ Wv)
{
    __shared__ float xs[32 * XPAD];
    __shared__ float ws[NCOLS * XPAD];

    const int bx = blockIdx.x;
    const int mat = bx / (32 * KSPLIT);
    const int rem = bx % (32 * KSPLIT);
    const int colbase = (rem / KSPLIT) * NCOLS;
    const int ks  = rem % KSPLIT;
    const int k0base = ks * KCHUNK;

    const float* W = (mat == 0) ? Wq : (mat == 1) ? Wk : Wv;

    const int tid  = threadIdx.x;
    const int lane = tid & 31;           // batch
    const int wid  = tid >> 5;           // warp -> col group of 8

    float acc[8];
    #pragma unroll
    for (int c = 0; c < 8; c++) acc[c] = 0.f;

    for (int s = 0; s < KCHUNK / 64; s++) {
        const int k0 = k0base + s * 64;
        #pragma unroll
        for (int r = 0; r < 2; r++) {
            int idx = r * 256 + tid;           // 0..511
            int b = idx >> 4, kv = idx & 15;
            float4 t = *(const float4*)(x + b * Dk + k0 + kv * 4);
            *(float4*)(xs + b * XPAD + kv * 4) = t;
        }
        #pragma unroll
        for (int r = 0; r < 4; r++) {
            int idx = r * 256 + tid;           // 0..1023
            int c = idx >> 4, kv = idx & 15;
            float4 t = *(const float4*)(W + (colbase + c) * Dk + k0 + kv * 4);
            *(float4*)(ws + c * XPAD + kv * 4) = t;
        }
        __syncthreads();

        const float* xrow  = xs + lane * XPAD;
        const float* wbase = ws + (wid * 8) * XPAD;

        #pragma unroll 4
        for (int k = 0; k < 64; k += 4) {
            float4 xv = *(const float4*)(xrow + k);
            #pragma unroll
            for (int c = 0; c < 8; c++) {
                float4 wv = *(const float4*)(wbase + c * XPAD + k);  // broadcast
                float a = acc[c];
                a = fmaf(xv.x, wv.x, a);
                a = fmaf(xv.y, wv.y, a);
                a = fmaf(xv.z, wv.z, a);
                a = fmaf(xv.w, wv.w, a);
                acc[c] = a;
            }
        }
        __syncthreads();
    }

    float* dst = g_part + (((mat * KSPLIT + ks) * Dk) + colbase + wid * 8) * Bk + lane;
    #pragma unroll
    for (int c = 0; c < 8; c++) dst[c * Bk] = acc[c];
}

// ---------------------------------------------------------------------------
// K1b: reduce over KSPLIT + bias + scale + transpose (R3 version).
// ---------------------------------------------------------------------------
__global__ __launch_bounds__(256, 1) void reduce_kernel(
    const float* __restrict__ bq,
    const float* __restrict__ bk,
    const float* __restrict__ bv)
{
    __shared__ float s[NCOLS][33];

    const int mat = blockIdx.x / 32;
    const int colbase = (blockIdx.x % 32) * NCOLS;
    const int tid = threadIdx.x;

    const float* bias; float* out; float scale;
    if (mat == 0)      { bias = bq; out = g_q2; scale = LOG2E; }
    else if (mat == 1) { bias = bk; out = g_k;  scale = 1.0f; }
    else               { bias = bv; out = g_v;  scale = 1.0f; }

    const float* src = g_part + (mat * KSPLIT * Dk + colbase) * Bk;

    #pragma unroll
    for (int it = 0; it < 8; it++) {
        int e = it * 256 + tid;
        int c = e >> 5, b = e & 31;
        float sum = 0.f;
        #pragma unroll
        for (int p = 0; p < KSPLIT; p++)
            sum += src[p * Dk * Bk + c * Bk + b];
        s[c][b] = sum;
    }
    __syncthreads();

    #pragma unroll
    for (int it = 0; it < 8; it++) {
        int e = it * 256 + tid;
        int b = e >> 6, c = e & 63;
        out[b * Dk + colbase + c] = (s[c][b] + bias[colbase + c]) * scale;
    }
}

// ---------------------------------------------------------------------------
// K2 (pass1): S_j = sum_i exp2(q2_i*k_j - m2_j).
// Block 512 thr: 128 j's x 4 i-segments (512 i each). Partials combined in smem.
// Grid (16, 32) -> 8192 resident warps (occupancy fix).
// ---------------------------------------------------------------------------
__global__ __launch_bounds__(512, 1) void pass1_kernel()
{
    __shared__ float4 q2s4[Dk / 4];          // 8 KB
    __shared__ float wmx[16], wmn[16];
    __shared__ float partS[3][128];          // i-segments 1..3

    const int b    = blockIdx.y;
    const int tid  = threadIdx.x;
    const int jq   = tid & 127;
    const int iseg = tid >> 7;               // 0..3
    const int j    = blockIdx.x * 128 + jq;
    const float4* q2 = (const float4*)(g_q2 + b * Dk);

    // cooperative q2 load + min/max (512 threads, 1 float4 each)
    float mx = -CUDART_INF_F, mn = CUDART_INF_F;
    {
        float4 v = q2[tid];
        q2s4[tid] = v;
        mx = fmaxf(fmaxf(v.x, v.y), fmaxf(v.z, v.w));
        mn = fminf(fminf(v.x, v.y), fminf(v.z, v.w));
    }
    #pragma unroll
    for (int o = 16; o; o >>= 1) {
        mx = fmaxf(mx, __shfl_xor_sync(0xffffffffu, mx, o));
        mn = fminf(mn, __shfl_xor_sync(0xffffffffu, mn, o));
    }
    if ((tid & 31) == 0) { wmx[tid >> 5] = mx; wmn[tid >> 5] = mn; }
    __syncthreads();
    mx = wmx[0]; mn = wmn[0];
    #pragma unroll
    for (int w = 1; w < 16; w++) {
        mx = fmaxf(mx, wmx[w]); mn = fminf(mn, wmn[w]);
    }

    const float kj    = g_k[b * Dk + j];
    const float negm2 = -((kj > 0.0f) ? mx : mn) * kj;   // exponent <= 0

    // this segment's i-range: 512 i's = 128 float4's
    const int i4base = iseg * 128;
    float a0 = 0.f, a1 = 0.f, a2 = 0.f, a3 = 0.f;
    #pragma unroll 2
    for (int i4 = 0; i4 < 128; i4++) {
        float4 q = q2s4[i4base + i4];                    // broadcast LDS.128
        a0 += ex2f(fmaf(q.x, kj, negm2));
        a1 += ex2f(fmaf(q.y, kj, negm2));
        a2 += ex2f(fmaf(q.z, kj, negm2));
        a3 += ex2f(fmaf(q.w, kj, negm2));
    }
    float part = (a0 + a1) + (a2 + a3);

    if (iseg > 0) partS[iseg - 1][jq] = part;
    __syncthreads();
    if (iseg == 0) {
        const float S = ((part + partS[0][jq]) + (partS[1][jq] + partS[2][jq])); // >= 1
        const float c = __fdividef(g_v[b * Dk + j], S);
        g_kmc[b * Dk + j] = make_float4(kj, negm2, c, 0.0f);
    }
}

// ---------------------------------------------------------------------------
// K3 (pass2): out[b][i] = sum_j c_j * exp2(q2_i*k_j - m2_j).
// Block 512 thr: 128 i's x 4 j-segments (512 j each). Partials combined in smem.
// ---------------------------------------------------------------------------
__global__ __launch_bounds__(512, 1) void pass2_kernel(float* __restrict__ out)
{
    __shared__ float4 kmcs[Dk];              // 32 KB
    __shared__ float partO[3][128];

    const int b    = blockIdx.y;
    const int tid  = threadIdx.x;
    const int iq   = tid & 127;
    const int jseg = tid >> 7;               // 0..3
    const int i    = blockIdx.x * 128 + iq;

    const float4* src = g_kmc + b * Dk;
    #pragma unroll
    for (int r = 0; r < 4; r++) kmcs[r * 512 + tid] = src[r * 512 + tid];
    __syncthreads();

    const float qi = g_q2[b * Dk + i];
    const int jbase = jseg * 512;

    float a0 = 0.f, a1 = 0.f, a2 = 0.f, a3 = 0.f;
    #pragma unroll 2
    for (int jj = 0; jj < 512; jj += 4) {
        float4 p0 = kmcs[jbase + jj + 0];
        float4 p1 = kmcs[jbase + jj + 1];
        float4 p2 = kmcs[jbase + jj + 2];
        float4 p3 = kmcs[jbase + jj + 3];
        a0 = fmaf(ex2f(fmaf(qi, p0.x, p0.y)), p0.z, a0);
        a1 = fmaf(ex2f(fmaf(qi, p1.x, p1.y)), p1.z, a1);
        a2 = fmaf(ex2f(fmaf(qi, p2.x, p2.y)), p2.z, a2);
        a3 = fmaf(ex2f(fmaf(qi, p3.x, p3.y)), p3.z, a3);
    }
    float part = (a0 + a1) + (a2 + a3);

    if (jseg > 0) partO[jseg - 1][iq] = part;
    __syncthreads();
    if (jseg == 0)
        out[b * Dk + i] = (part + partO[0][iq]) + (partO[1][iq] + partO[2][iq]);
}

// ---------------------------------------------------------------------------
extern "C" void kernel_launch(void* const* d_in, const int* in_sizes, int n_in,
                              void* d_out, int out_size)
{
    (void)in_sizes; (void)n_in; (void)out_size;
    const float* x  = (const float*)d_in[0];
    const float* Wq = (const float*)d_in[1];
    const float* bq = (const float*)d_in[2];
    const float* Wk = (const float*)d_in[3];
    const float* bk = (const float*)d_in[4];
    const float* Wv = (const float*)d_in[5];
    const float* bv = (const float*)d_in[6];
    float* out = (float*)d_out;

    proj_kernel<<<3 * 32 * KSPLIT, 256>>>(x, Wq, Wk, Wv);
    reduce_kernel<<<3 * 32, 256>>>(bq, bk, bv);

    dim3 grid_s(Dk / 128, Bk);   // (16, 32)
    pass1_kernel<<<grid_s, 512>>>();
    pass2_kernel<<<grid_s, 512>>>(out);
}

// round 10
// speedup vs baseline: 1.7368x; 1.0328x over previous
#include <cuda_runtime.h>
#include <math_constants.h>

#define Dk 2048
#define Bk 32
#define LOG2E 1.4426950408889634f
#define KSPLIT 8
#define KCHUNK (Dk / KSPLIT)        // 256
#define NCOLS  64
#define XPAD   68                   // 272B rows: 16B-aligned, conflict-free

typedef unsigned long long u64;
typedef unsigned int u32;

// Scratch (no allocations allowed) -------------------------------------------
__device__ float  g_part[3 * KSPLIT * Dk * Bk];  // [mat][ks][col][b]
__device__ float  g_q2[Bk * Dk];   // (x@WqT + bq) * log2e
__device__ float  g_k [Bk * Dk];
__device__ float  g_v [Bk * Dk];
__device__ float4 g_kmp4[Bk * Dk / 2];           // pairs {k0,k1,m0,m1}
__device__ float4 g_c4 [Bk * Dk / 4];            // c packed 4-wide

__device__ __forceinline__ float ex2f(float x) {
    float r; asm("ex2.approx.f32 %0, %1;" : "=f"(r) : "f"(x)); return r;
}
__device__ __forceinline__ u64 pk2(float a, float b) {
    u64 r;
    asm("mov.b64 %0, {%1,%2};" : "=l"(r)
        : "r"(__float_as_uint(a)), "r"(__float_as_uint(b)));
    return r;
}
__device__ __forceinline__ void upk2f(u64 v, float &a, float &b) {
    u32 x, y;
    asm("mov.b64 {%0,%1}, %2;" : "=r"(x), "=r"(y) : "l"(v));
    a = __uint_as_float(x); b = __uint_as_float(y);
}
#define FMAX2(d,a,b,c) asm("fma.rn.f32x2 %0, %1, %2, %3;" : "=l"(d) : "l"(a), "l"(b), "l"(c))

// ---------------------------------------------------------------------------
// K1: split-K projection GEMM partials (R3/R9 version, scalar FMA). UNCHANGED.
// ---------------------------------------------------------------------------
__global__ __launch_bounds__(256, 1) void proj_kernel(
    const float* __restrict__ x,
    const float* __restrict__ Wq,
    const float* __restrict__ Wk,
    const float* __restrict__ Wv)
{
    __shared__ float xs[32 * XPAD];
    __shared__ float ws[NCOLS * XPAD];

    const int bx = blockIdx.x;
    const int mat = bx / (32 * KSPLIT);
    const int rem = bx % (32 * KSPLIT);
    const int colbase = (rem / KSPLIT) * NCOLS;
    const int ks  = rem % KSPLIT;
    const int k0base = ks * KCHUNK;

    const float* W = (mat == 0) ? Wq : (mat == 1) ? Wk : Wv;

    const int tid  = threadIdx.x;
    const int lane = tid & 31;           // batch
    const int wid  = tid >> 5;           // warp -> col group of 8

    float acc[8];
    #pragma unroll
    for (int c = 0; c < 8; c++) acc[c] = 0.f;

    for (int s = 0; s < KCHUNK / 64; s++) {
        const int k0 = k0base + s * 64;
        #pragma unroll
        for (int r = 0; r < 2; r++) {
            int idx = r * 256 + tid;
            int b = idx >> 4, kv = idx & 15;
            float4 t = *(const float4*)(x + b * Dk + k0 + kv * 4);
            *(float4*)(xs + b * XPAD + kv * 4) = t;
        }
        #pragma unroll
        for (int r = 0; r < 4; r++) {
            int idx = r * 256 + tid;
            int c = idx >> 4, kv = idx & 15;
            float4 t = *(const float4*)(W + (colbase + c) * Dk + k0 + kv * 4);
            *(float4*)(ws + c * XPAD + kv * 4) = t;
        }
        __syncthreads();

        const float* xrow  = xs + lane * XPAD;
        const float* wbase = ws + (wid * 8) * XPAD;

        #pragma unroll 4
        for (int k = 0; k < 64; k += 4) {
            float4 xv = *(const float4*)(xrow + k);
            #pragma unroll
            for (int c = 0; c < 8; c++) {
                float4 wv = *(const float4*)(wbase + c * XPAD + k);  // broadcast
                float a = acc[c];
                a = fmaf(xv.x, wv.x, a);
                a = fmaf(xv.y, wv.y, a);
                a = fmaf(xv.z, wv.z, a);
                a = fmaf(xv.w, wv.w, a);
                acc[c] = a;
            }
        }
        __syncthreads();
    }

    float* dst = g_part + (((mat * KSPLIT + ks) * Dk) + colbase + wid * 8) * Bk + lane;
    #pragma unroll
    for (int c = 0; c < 8; c++) dst[c * Bk] = acc[c];
}

// ---------------------------------------------------------------------------
// K1b: reduce over KSPLIT + bias + scale + transpose. UNCHANGED.
// ---------------------------------------------------------------------------
__global__ __launch_bounds__(256, 1) void reduce_kernel(
    const float* __restrict__ bq,
    const float* __restrict__ bk,
    const float* __restrict__ bv)
{
    __shared__ float s[NCOLS][33];

    const int mat = blockIdx.x / 32;
    const int colbase = (blockIdx.x % 32) * NCOLS;
    const int tid = threadIdx.x;

    const float* bias; float* out; float scale;
    if (mat == 0)      { bias = bq; out = g_q2; scale = LOG2E; }
    else if (mat == 1) { bias = bk; out = g_k;  scale = 1.0f; }
    else               { bias = bv; out = g_v;  scale = 1.0f; }

    const float* src = g_part + (mat * KSPLIT * Dk + colbase) * Bk;

    #pragma unroll
    for (int it = 0; it < 8; it++) {
        int e = it * 256 + tid;
        int c = e >> 5, b = e & 31;
        float sum = 0.f;
        #pragma unroll
        for (int p = 0; p < KSPLIT; p++)
            sum += src[p * Dk * Bk + c * Bk + b];
        s[c][b] = sum;
    }
    __syncthreads();

    #pragma unroll
    for (int it = 0; it < 8; it++) {
        int e = it * 256 + tid;
        int b = e >> 6, c = e & 63;
        out[b * Dk + colbase + c] = (s[c][b] + bias[colbase + c]) * scale;
    }
}

// ---------------------------------------------------------------------------
// K2 (pass1): S_j = sum_i exp2(q2_i*k_j - m2_j).
// Block 512: 128 j x 4 i-segments. f32x2 arg FMA; pure MUFU exp.
// Writes pair-packed {k0,k1,m0,m1} + c4.
// ---------------------------------------------------------------------------
__global__ __launch_bounds__(512, 3) void pass1_kernel()
{
    __shared__ float4 q2s4[Dk / 4];          // 8 KB
    __shared__ float wmx[16], wmn[16];
    __shared__ float partS[3][128];

    const int b    = blockIdx.y;
    const int tid  = threadIdx.x;
    const int jq   = tid & 127;
    const int iseg = tid >> 7;               // 0..3
    const int j    = blockIdx.x * 128 + jq;
    const float4* q2 = (const float4*)(g_q2 + b * Dk);

    float mx = -CUDART_INF_F, mn = CUDART_INF_F;
    {
        float4 v = q2[tid];
        q2s4[tid] = v;
        mx = fmaxf(fmaxf(v.x, v.y), fmaxf(v.z, v.w));
        mn = fminf(fminf(v.x, v.y), fminf(v.z, v.w));
    }
    #pragma unroll
    for (int o = 16; o; o >>= 1) {
        mx = fmaxf(mx, __shfl_xor_sync(0xffffffffu, mx, o));
        mn = fminf(mn, __shfl_xor_sync(0xffffffffu, mn, o));
    }
    if ((tid & 31) == 0) { wmx[tid >> 5] = mx; wmn[tid >> 5] = mn; }
    __syncthreads();
    mx = wmx[0]; mn = wmn[0];
    #pragma unroll
    for (int w = 1; w < 16; w++) {
        mx = fmaxf(mx, wmx[w]); mn = fminf(mn, wmn[w]);
    }

    const float kj    = g_k[b * Dk + j];
    const float negm2 = -((kj > 0.0f) ? mx : mn) * kj;   // exponent <= 0
    const u64 kk = pk2(kj, kj);
    const u64 mm = pk2(negm2, negm2);

    const int i4base = iseg * 128;
    const double2* qp = (const double2*)(q2s4 + i4base);  // 2 u64 per float4

    float a0 = 0.f, a1 = 0.f, a2 = 0.f, a3 = 0.f;
    #pragma unroll 2
    for (int i4 = 0; i4 < 128; i4++) {
        double2 qv = qp[i4];
        u64 q01 = __double_as_longlong(qv.x);
        u64 q23 = __double_as_longlong(qv.y);
        u64 e01, e23;
        FMAX2(e01, kk, q01, mm);                 // {q0*k+m, q1*k+m}
        FMAX2(e23, kk, q23, mm);
        float x0, x1, x2, x3;
        upk2f(e01, x0, x1); upk2f(e23, x2, x3);
        a0 += ex2f(x0);
        a1 += ex2f(x1);
        a2 += ex2f(x2);
        a3 += ex2f(x3);
    }
    float part = (a0 + a1) + (a2 + a3);

    if (iseg > 0) partS[iseg - 1][jq] = part;
    __syncthreads();
    if (iseg == 0) {
        const float S = (part + partS[0][jq]) + (partS[1][jq] + partS[2][jq]);  // >= 1
        const float c = __fdividef(g_v[b * Dk + j], S);
        float* kmpf = (float*)g_kmp4;
        int base = (b * (Dk >> 1) + (j >> 1)) * 4 + (j & 1);
        kmpf[base]     = kj;
        kmpf[base + 2] = negm2;
        ((float*)g_c4)[b * Dk + j] = c;
    }
}

// ---------------------------------------------------------------------------
// K3 (pass2): out[b][i] = sum_j c_j * exp2(q2_i*k_j - m2_j).
// Block 512: 128 i x 4 j-segments (512 j each). f32x2 arg FMA, pure MUFU exp.
// ---------------------------------------------------------------------------
__global__ __launch_bounds__(512, 3) void pass2_kernel(float* __restrict__ out)
{
    __shared__ float4 kmps[Dk / 2];          // 16 KB {k0,k1,m0,m1} per 2 j
    __shared__ float4 cs[Dk / 4];            // 8 KB
    __shared__ float partO[3][128];

    const int b    = blockIdx.y;
    const int tid  = threadIdx.x;
    const int iq   = tid & 127;
    const int jseg = tid >> 7;               // 0..3
    const int i    = blockIdx.x * 128 + iq;

    const float4* kmsrc = g_kmp4 + b * (Dk / 2);
    const float4* csrc  = g_c4  + b * (Dk / 4);
    #pragma unroll
    for (int r = 0; r < 2; r++) kmps[r * 512 + tid] = kmsrc[r * 512 + tid];
    if (tid < Dk / 4) cs[tid] = csrc[tid];
    __syncthreads();

    const float qi = g_q2[b * Dk + i];
    const u64 qq = pk2(qi, qi);

    const int jbase = jseg * 512;
    const double2* kmp = (const double2*)(kmps + (jbase >> 1));  // per float4: (k0,k1),(m0,m1)
    const float4*  cp  = cs + (jbase >> 2);

    float a0 = 0.f, a1 = 0.f, a2 = 0.f, a3 = 0.f;
    #pragma unroll 2
    for (int jj = 0; jj < 128; jj++) {       // 4 j per iter
        double2 km0 = kmp[jj * 2 + 0];
        double2 km1 = kmp[jj * 2 + 1];
        float4  c4  = cp[jj];
        u64 e01, e23;
        FMAX2(e01, qq, __double_as_longlong(km0.x), __double_as_longlong(km0.y));
        FMAX2(e23, qq, __double_as_longlong(km1.x), __double_as_longlong(km1.y));
        float x0, x1, x2, x3;
        upk2f(e01, x0, x1); upk2f(e23, x2, x3);
        a0 = fmaf(ex2f(x0), c4.x, a0);
        a1 = fmaf(ex2f(x1), c4.y, a1);
        a2 = fmaf(ex2f(x2), c4.z, a2);
        a3 = fmaf(ex2f(x3), c4.w, a3);
    }
    float part = (a0 + a1) + (a2 + a3);

    if (jseg > 0) partO[jseg - 1][iq] = part;
    __syncthreads();
    if (jseg == 0)
        out[b * Dk + i] = (part + partO[0][iq]) + (partO[1][iq] + partO[2][iq]);
}

// ---------------------------------------------------------------------------
extern "C" void kernel_launch(void* const* d_in, const int* in_sizes, int n_in,
                              void* d_out, int out_size)
{
    (void)in_sizes; (void)n_in; (void)out_size;
    const float* x  = (const float*)d_in[0];
    const float* Wq = (const float*)d_in[1];
    const float* bq = (const float*)d_in[2];
    const float* Wk = (const float*)d_in[3];
    const float* bk = (const float*)d_in[4];
    const float* Wv = (const float*)d_in[5];
    const float* bv = (const float*)d_in[6];
    float* out = (float*)d_out;

    proj_kernel<<<3 * 32 * KSPLIT, 256>>>(x, Wq, Wk, Wv);
    reduce_kernel<<<3 * 32, 256>>>(bq, bk, bv);

    dim3 grid_s(Dk / 128, Bk);   // (16, 32)
    pass1_kernel<<<grid_s, 512>>>();
    pass2_kernel<<<grid_s, 512>>>(out);
}

// round 12
// speedup vs baseline: 1.8038x; 1.0386x over previous
#include <cuda_runtime.h>
#include <math_constants.h>

#define Dk 2048
#define Bk 32
#define LOG2E 1.4426950408889634f
#define KSPLIT 8
#define KCHUNK (Dk / KSPLIT)        // 256
#define NCOLS  64
#define XPAD   68                   // 272B rows: 16B-aligned, conflict-free

typedef unsigned long long u64;
typedef unsigned int u32;

// Scratch (no allocations allowed) -------------------------------------------
__device__ float  g_part[3 * KSPLIT * Dk * Bk];  // [mat][ks][col][b]
__device__ float  g_q2[Bk * Dk];   // (x@WqT + bq) * log2e
__device__ float  g_k [Bk * Dk];
__device__ float  g_v [Bk * Dk];
__device__ float4 g_kmp4[Bk * Dk / 2];           // pairs {k0,k1,m0,m1}
__device__ float4 g_c4 [Bk * Dk / 4];            // c packed 4-wide

__device__ __forceinline__ float ex2f(float x) {
    float r; asm("ex2.approx.f32 %0, %1;" : "=f"(r) : "f"(x)); return r;
}
__device__ __forceinline__ u64 pk2(float a, float b) {
    u64 r;
    asm("mov.b64 %0, {%1,%2};" : "=l"(r)
        : "r"(__float_as_uint(a)), "r"(__float_as_uint(b)));
    return r;
}
__device__ __forceinline__ void upk2f(u64 v, float &a, float &b) {
    u32 x, y;
    asm("mov.b64 {%0,%1}, %2;" : "=r"(x), "=r"(y) : "l"(v));
    a = __uint_as_float(x); b = __uint_as_float(y);
}
#define FMAX2(d,a,b,c) asm("fma.rn.f32x2 %0, %1, %2, %3;" : "=l"(d) : "l"(a), "l"(b), "l"(c))

// ---------------------------------------------------------------------------
// K1: split-K projection GEMM partials. UNCHANGED.
// ---------------------------------------------------------------------------
__global__ __launch_bounds__(256, 1) void proj_kernel(
    const float* __restrict__ x,
    const float* __restrict__ Wq,
    const float* __restrict__ Wk,
    const float* __restrict__ Wv)
{
    __shared__ float xs[32 * XPAD];
    __shared__ float ws[NCOLS * XPAD];

    const int bx = blockIdx.x;
    const int mat = bx / (32 * KSPLIT);
    const int rem = bx % (32 * KSPLIT);
    const int colbase = (rem / KSPLIT) * NCOLS;
    const int ks  = rem % KSPLIT;
    const int k0base = ks * KCHUNK;

    const float* W = (mat == 0) ? Wq : (mat == 1) ? Wk : Wv;

    const int tid  = threadIdx.x;
    const int lane = tid & 31;           // batch
    const int wid  = tid >> 5;           // warp -> col group of 8

    float acc[8];
    #pragma unroll
    for (int c = 0; c < 8; c++) acc[c] = 0.f;

    for (int s = 0; s < KCHUNK / 64; s++) {
        const int k0 = k0base + s * 64;
        #pragma unroll
        for (int r = 0; r < 2; r++) {
            int idx = r * 256 + tid;
            int b = idx >> 4, kv = idx & 15;
            float4 t = *(const float4*)(x + b * Dk + k0 + kv * 4);
            *(float4*)(xs + b * XPAD + kv * 4) = t;
        }
        #pragma unroll
        for (int r = 0; r < 4; r++) {
            int idx = r * 256 + tid;
            int c = idx >> 4, kv = idx & 15;
            float4 t = *(const float4*)(W + (colbase + c) * Dk + k0 + kv * 4);
            *(float4*)(ws + c * XPAD + kv * 4) = t;
        }
        __syncthreads();

        const float* xrow  = xs + lane * XPAD;
        const float* wbase = ws + (wid * 8) * XPAD;

        #pragma unroll 4
        for (int k = 0; k < 64; k += 4) {
            float4 xv = *(const float4*)(xrow + k);
            #pragma unroll
            for (int c = 0; c < 8; c++) {
                float4 wv = *(const float4*)(wbase + c * XPAD + k);  // broadcast
                float a = acc[c];
                a = fmaf(xv.x, wv.x, a);
                a = fmaf(xv.y, wv.y, a);
                a = fmaf(xv.z, wv.z, a);
                a = fmaf(xv.w, wv.w, a);
                acc[c] = a;
            }
        }
        __syncthreads();
    }

    float* dst = g_part + (((mat * KSPLIT + ks) * Dk) + colbase + wid * 8) * Bk + lane;
    #pragma unroll
    for (int c = 0; c < 8; c++) dst[c * Bk] = acc[c];
}

// ---------------------------------------------------------------------------
// K1b: reduce over KSPLIT + bias + scale + transpose. UNCHANGED.
// ---------------------------------------------------------------------------
__global__ __launch_bounds__(256, 1) void reduce_kernel(
    const float* __restrict__ bq,
    const float* __restrict__ bk,
    const float* __restrict__ bv)
{
    __shared__ float s[NCOLS][33];

    const int mat = blockIdx.x / 32;
    const int colbase = (blockIdx.x % 32) * NCOLS;
    const int tid = threadIdx.x;

    const float* bias; float* out; float scale;
    if (mat == 0)      { bias = bq; out = g_q2; scale = LOG2E; }
    else if (mat == 1) { bias = bk; out = g_k;  scale = 1.0f; }
    else               { bias = bv; out = g_v;  scale = 1.0f; }

    const float* src = g_part + (mat * KSPLIT * Dk + colbase) * Bk;

    #pragma unroll
    for (int it = 0; it < 8; it++) {
        int e = it * 256 + tid;
        int c = e >> 5, b = e & 31;
        float sum = 0.f;
        #pragma unroll
        for (int p = 0; p < KSPLIT; p++)
            sum += src[p * Dk * Bk + c * Bk + b];
        s[c][b] = sum;
    }
    __syncthreads();

    #pragma unroll
    for (int it = 0; it < 8; it++) {
        int e = it * 256 + tid;
        int b = e >> 6, c = e & 63;
        out[b * Dk + colbase + c] = (s[c][b] + bias[colbase + c]) * scale;
    }
}

// ---------------------------------------------------------------------------
// K2 (pass1): S_j = sum_i exp2(q2_i*k_j - m2_j).
// Grid (8,32) = 256 blocks (single wave). Block 512 = 128 j x 4 i-segments,
// TWO j-chunks per block reusing the q2 tile + min/max.
// ---------------------------------------------------------------------------
__global__ __launch_bounds__(512, 3) void pass1_kernel()
{
    __shared__ float4 q2s4[Dk / 4];          // 8 KB
    __shared__ float wmx[16], wmn[16];
    __shared__ float partS[2][3][128];       // [chunk][iseg-1][jq]

    const int b    = blockIdx.y;
    const int tid  = threadIdx.x;
    const int jq   = tid & 127;
    const int iseg = tid >> 7;               // 0..3
    const float4* q2 = (const float4*)(g_q2 + b * Dk);

    float mx = -CUDART_INF_F, mn = CUDART_INF_F;
    {
        float4 v = q2[tid];
        q2s4[tid] = v;
        mx = fmaxf(fmaxf(v.x, v.y), fmaxf(v.z, v.w));
        mn = fminf(fminf(v.x, v.y), fminf(v.z, v.w));
    }
    #pragma unroll
    for (int o = 16; o; o >>= 1) {
        mx = fmaxf(mx, __shfl_xor_sync(0xffffffffu, mx, o));
        mn = fminf(mn, __shfl_xor_sync(0xffffffffu, mn, o));
    }
    if ((tid & 31) == 0) { wmx[tid >> 5] = mx; wmn[tid >> 5] = mn; }
    __syncthreads();
    mx = wmx[0]; mn = wmn[0];
    #pragma unroll
    for (int w = 1; w < 16; w++) {
        mx = fmaxf(mx, wmx[w]); mn = fminf(mn, wmn[w]);
    }

    const int i4base = iseg * 128;
    const double2* qp = (const double2*)(q2s4 + i4base);

    #pragma unroll 1
    for (int ch = 0; ch < 2; ch++) {
        const int j = blockIdx.x * 256 + ch * 128 + jq;

        const float kj    = g_k[b * Dk + j];
        const float negm2 = -((kj > 0.0f) ? mx : mn) * kj;   // exponent <= 0
        const u64 kk = pk2(kj, kj);
        const u64 mm = pk2(negm2, negm2);

        float a0 = 0.f, a1 = 0.f, a2 = 0.f, a3 = 0.f;
        #pragma unroll 2
        for (int i4 = 0; i4 < 128; i4++) {
            double2 qv = qp[i4];
            u64 q01 = __double_as_longlong(qv.x);
            u64 q23 = __double_as_longlong(qv.y);
            u64 e01, e23;
            FMAX2(e01, kk, q01, mm);
            FMAX2(e23, kk, q23, mm);
            float x0, x1, x2, x3;
            upk2f(e01, x0, x1); upk2f(e23, x2, x3);
            a0 += ex2f(x0);
            a1 += ex2f(x1);
            a2 += ex2f(x2);
            a3 += ex2f(x3);
        }
        float part = (a0 + a1) + (a2 + a3);

        if (iseg > 0) partS[ch][iseg - 1][jq] = part;
        __syncthreads();
        if (iseg == 0) {
            const float S = (part + partS[ch][0][jq]) +
                            (partS[ch][1][jq] + partS[ch][2][jq]);   // >= 1
            const float c = __fdividef(g_v[b * Dk + j], S);
            float* kmpf = (float*)g_kmp4;
            int base = (b * (Dk >> 1) + (j >> 1)) * 4 + (j & 1);
            kmpf[base]     = kj;
            kmpf[base + 2] = negm2;
            ((float*)g_c4)[b * Dk + j] = c;
        }
    }
}

// ---------------------------------------------------------------------------
// K3 (pass2): out[b][i] = sum_j c_j * exp2(q2_i*k_j - m2_j).
// Grid (8,32) = 256 blocks. Block 512 = 128 i x 4 j-segments,
// TWO i-chunks per block reusing the kmc/c tiles.
// ---------------------------------------------------------------------------
__global__ __launch_bounds__(512, 3) void pass2_kernel(float* __restrict__ out)
{
    __shared__ float4 kmps[Dk / 2];          // 16 KB {k0,k1,m0,m1} per 2 j
    __shared__ float4 cs[Dk / 4];            // 8 KB
    __shared__ float partO[2][3][128];       // [chunk][jseg-1][iq]

    const int b    = blockIdx.y;
    const int tid  = threadIdx.x;
    const int iq   = tid & 127;
    const int jseg = tid >> 7;               // 0..3

    const float4* kmsrc = g_kmp4 + b * (Dk / 2);
    const float4* csrc  = g_c4  + b * (Dk / 4);
    #pragma unroll
    for (int r = 0; r < 2; r++) kmps[r * 512 + tid] = kmsrc[r * 512 + tid];
    if (tid < Dk / 4) cs[tid] = csrc[tid];
    __syncthreads();

    const int jbase = jseg * 512;
    const double2* kmp = (const double2*)(kmps + (jbase >> 1));
    const float4*  cp  = cs + (jbase >> 2);

    #pragma unroll 1
    for (int ch = 0; ch < 2; ch++) {
        const int i = blockIdx.x * 256 + ch * 128 + iq;
        const float qi = g_q2[b * Dk + i];
        const u64 qq = pk2(qi, qi);

        float a0 = 0.f, a1 = 0.f, a2 = 0.f, a3 = 0.f;
        #pragma unroll 2
        for (int jj = 0; jj < 128; jj++) {   // 4 j per iter
            double2 km0 = kmp[jj * 2 + 0];
            double2 km1 = kmp[jj * 2 + 1];
            float4  c4  = cp[jj];
            u64 e01, e23;
            FMAX2(e01, qq, __double_as_longlong(km0.x), __double_as_longlong(km0.y));
            FMAX2(e23, qq, __double_as_longlong(km1.x), __double_as_longlong(km1.y));
            float x0, x1, x2, x3;
            upk2f(e01, x0, x1); upk2f(e23, x2, x3);
            a0 = fmaf(ex2f(x0), c4.x, a0);
            a1 = fmaf(ex2f(x1), c4.y, a1);
            a2 = fmaf(ex2f(x2), c4.z, a2);
            a3 = fmaf(ex2f(x3), c4.w, a3);
        }
        float part = (a0 + a1) + (a2 + a3);

        if (jseg > 0) partO[ch][jseg - 1][iq] = part;
        __syncthreads();
        if (jseg == 0)
            out[b * Dk + i] = (part + partO[ch][0][iq]) +
                              (partO[ch][1][iq] + partO[ch][2][iq]);
    }
}

// ---------------------------------------------------------------------------
extern "C" void kernel_launch(void* const* d_in, const int* in_sizes, int n_in,
                              void* d_out, int out_size)
{
    (void)in_sizes; (void)n_in; (void)out_size;
    const float* x  = (const float*)d_in[0];
    const float* Wq = (const float*)d_in[1];
    const float* bq = (const float*)d_in[2];
    const float* Wk = (const float*)d_in[3];
    const float* bk = (const float*)d_in[4];
    const float* Wv = (const float*)d_in[5];
    const float* bv = (const float*)d_in[6];
    float* out = (float*)d_out;

    proj_kernel<<<3 * 32 * KSPLIT, 256>>>(x, Wq, Wk, Wv);
    reduce_kernel<<<3 * 32, 256>>>(bq, bk, bv);

    dim3 grid_s(Dk / 256, Bk);   // (8, 32) = 256 blocks, single wave
    pass1_kernel<<<grid_s, 512>>>();
    pass2_kernel<<<grid_s, 512>>>(out);
}